// round 9
// baseline (speedup 1.0000x reference)
#include <cuda_runtime.h>
#include <math.h>
#include <cstdint>

#define BB    2048
#define NN    62
#define FIN   128
#define HID   512
#define HEADS 8
#define FOUT  64
#define NROWS (BB * NN)   // 126976

__device__ float g_hx[(size_t)NROWS * HID];
__device__ float g_h [(size_t)NROWS * HID];
__device__ float g_Wr[(size_t)3 * HEADS * HID * FOUT];
__device__ float g_Wmr[FIN * HID];
__device__ float g_cs[HID];

// ===========================================================================
// helpers
// ===========================================================================
__device__ __forceinline__ uint32_t smem_u32(const void* p) {
    uint32_t a;
    asm("{ .reg .u64 t; cvta.to.shared.u64 t, %1; cvt.u32.u64 %0, t; }"
        : "=r"(a) : "l"(p));
    return a;
}
__device__ __forceinline__ float tf32r(float x) {
    uint32_t u;
    asm("cvt.rna.tf32.f32 %0, %1;" : "=r"(u) : "f"(x));
    return __uint_as_float(u);
}
__device__ __forceinline__ void cp_async16(uint32_t dst, const void* src) {
    asm volatile("cp.async.cg.shared.global [%0], [%1], 16;"
                 :: "r"(dst), "l"(src) : "memory");
}
__device__ __forceinline__ void cp_commit() {
    asm volatile("cp.async.commit_group;" ::: "memory");
}
template <int N>
__device__ __forceinline__ void cp_wait() {
    asm volatile("cp.async.wait_group %0;" :: "n"(N) : "memory");
}
__device__ __forceinline__ void mma_tf32(float* c, const uint32_t* a, const uint32_t* b) {
    asm volatile(
        "mma.sync.aligned.m16n8k8.row.col.f32.tf32.tf32.f32 "
        "{%0,%1,%2,%3}, {%4,%5,%6,%7}, {%8,%9}, {%0,%1,%2,%3};"
        : "+f"(c[0]), "+f"(c[1]), "+f"(c[2]), "+f"(c[3])
        : "r"(a[0]), "r"(a[1]), "r"(a[2]), "r"(a[3]), "r"(b[0]), "r"(b[1]));
}

// ===========================================================================
// K0 kernels: tf32 rounding of operands
// ===========================================================================
__global__ void k0_round_w(const float* __restrict__ Wg) {
    int i = blockIdx.x * 1024 + threadIdx.x;
    if (i < 3 * HEADS * HID * FOUT) g_Wr[i] = tf32r(Wg[i]);
}
__global__ void k0_round_x(const float* __restrict__ x) {
    size_t i = ((size_t)blockIdx.x * 256 + threadIdx.x) * 4;
    float4 v = *(const float4*)(x + i);
    v.x = tf32r(v.x); v.y = tf32r(v.y); v.z = tf32r(v.z); v.w = tf32r(v.w);
    *(float4*)(g_h + i) = v;
}
__global__ void k0_round_wm(const float* __restrict__ Wm) {
    int i = blockIdx.x * 1024 + threadIdx.x;
    if (i < FIN * HID) g_Wmr[i] = tf32r(Wm[i]);
}
__global__ void k0_colsum_wm() {
    int c = threadIdx.x;
    float s = 0.f;
    for (int k = 0; k < FIN; k++) s += g_Wmr[k * HID + c];
    g_cs[c] = s;
}

// ===========================================================================
// K1 tile config (tf32 GEMM with BN-affine epilogue)
// ===========================================================================
#define TM 128
#define TN 128
#define KC 32
#define NBUF 4
#define A_STRIDE 36
#define B_STRIDE 136
#define A_BYTES (TM * A_STRIDE * 4)
#define B_BYTES (KC * B_STRIDE * 4)
#define STAGE_BYTES (A_BYTES + B_BYTES)
#define K1_SMEM (NBUF * STAGE_BYTES)

__global__ __launch_bounds__(256, 1) void k1_mma(
    const float* __restrict__ gamma, const float* __restrict__ beta,
    const float* __restrict__ mean,  const float* __restrict__ var,
    const float* __restrict__ bm)
{
    extern __shared__ __align__(16) char smem[];
    const int NS_K = FIN / KC;   // 4
    const int tid  = threadIdx.x;
    const int lane = tid & 31;
    const int wid  = tid >> 5;
    const int wm   = wid & 3;
    const int wn   = wid >> 2;
    const int n0   = blockIdx.x * TN;
    const int row0 = blockIdx.y * TM;
    const uint32_t sbase = smem_u32(smem);

    auto issue_stage = [&](int s) {
        const int p = s & (NBUF - 1);
        const float* Ag = g_h + (size_t)row0 * FIN + s * KC;
        const uint32_t Ad = sbase + p * STAGE_BYTES;
#pragma unroll
        for (int i = 0; i < 4; i++) {
            int idx = tid + i * 256;
            int r = idx >> 3, k4 = idx & 7;
            cp_async16(Ad + r * (A_STRIDE * 4) + k4 * 16,
                       Ag + (size_t)r * FIN + k4 * 4);
        }
        const uint32_t Bd = sbase + p * STAGE_BYTES + A_BYTES;
#pragma unroll
        for (int i = 0; i < 4; i++) {
            int idx = tid + i * 256;
            int k = idx >> 5, n4 = idx & 31;
            cp_async16(Bd + k * (B_STRIDE * 4) + n4 * 16,
                       g_Wmr + (size_t)(s * KC + k) * HID + n0 + n4 * 4);
        }
    };

    float acc[2][8][4];
#pragma unroll
    for (int mt = 0; mt < 2; mt++)
#pragma unroll
        for (int nt = 0; nt < 8; nt++)
#pragma unroll
            for (int q = 0; q < 4; q++) acc[mt][nt][q] = 0.f;

#pragma unroll
    for (int s = 0; s < NBUF - 1; s++) { issue_stage(s); cp_commit(); }

#pragma unroll 1
    for (int s = 0; s < NS_K; s++) {
        if (s < NS_K - 2)       cp_wait<2>();
        else if (s == NS_K - 2) cp_wait<1>();
        else                    cp_wait<0>();
        __syncthreads();
        if (s + NBUF - 1 < NS_K) issue_stage(s + NBUF - 1);
        cp_commit();

        const float* As = (const float*)(smem + (s & (NBUF - 1)) * STAGE_BYTES);
        const float* Bs = As + TM * A_STRIDE;

#pragma unroll
        for (int ks = 0; ks < KC / 8; ks++) {
            const int kb = ks * 8;
            uint32_t a[2][4], b[8][2];
#pragma unroll
            for (int mt = 0; mt < 2; mt++) {
                int r = wm * 32 + mt * 16 + (lane >> 2);
                int k = kb + (lane & 3);
                a[mt][0] = __float_as_uint(As[r * A_STRIDE + k]);
                a[mt][1] = __float_as_uint(As[(r + 8) * A_STRIDE + k]);
                a[mt][2] = __float_as_uint(As[r * A_STRIDE + k + 4]);
                a[mt][3] = __float_as_uint(As[(r + 8) * A_STRIDE + k + 4]);
            }
#pragma unroll
            for (int nt = 0; nt < 8; nt++) {
                int c = wn * 64 + nt * 8 + (lane >> 2);
                int k = kb + (lane & 3);
                b[nt][0] = __float_as_uint(Bs[k * B_STRIDE + c]);
                b[nt][1] = __float_as_uint(Bs[(k + 4) * B_STRIDE + c]);
            }
#pragma unroll
            for (int mt = 0; mt < 2; mt++)
#pragma unroll
                for (int nt = 0; nt < 8; nt++)
                    mma_tf32(acc[mt][nt], a[mt], b[nt]);
        }
    }

    const int rbase = wm * 32 + (lane >> 2);
    float sv[4], tv[4];
#pragma unroll
    for (int q = 0; q < 4; q++) {
        int r = row0 + rbase + q * 8;
        int n = r % NN;
        float sc = gamma[n] * rsqrtf(var[n] + 1e-5f);
        sv[q] = sc;
        tv[q] = beta[n] - mean[n] * sc;
    }
#pragma unroll
    for (int mt = 0; mt < 2; mt++) {
        int r = row0 + rbase + mt * 16;
#pragma unroll
        for (int nt = 0; nt < 8; nt++) {
            int c = n0 + wn * 64 + nt * 8 + 2 * (lane & 3);
            float cs0 = g_cs[c], cs1 = g_cs[c + 1];
            float b0 = bm[c], b1 = bm[c + 1];
            int q0 = mt * 2, q1 = mt * 2 + 1;
            *(float2*)&g_hx[(size_t)r * HID + c] = make_float2(
                tf32r(sv[q0] * acc[mt][nt][0] + tv[q0] * cs0 + b0),
                tf32r(sv[q0] * acc[mt][nt][1] + tv[q0] * cs1 + b1));
            *(float2*)&g_hx[(size_t)(r + 8) * HID + c] = make_float2(
                tf32r(sv[q1] * acc[mt][nt][2] + tv[q1] * cs0 + b0),
                tf32r(sv[q1] * acc[mt][nt][3] + tv[q1] * cs1 + b1));
        }
    }
}

// ===========================================================================
// K24: fused per-(head, b) layer kernel.
//   phase 1: h = hx[b] @ W[head]  (62x64, K=512; cp.async double-buffered
//            K-chunks of 64; 8 warps, 16x32 MMA tiles; h stays in smem)
//   phase 2: round-8 attention (f1/f2, masked exp, colsum fold, 64^3 MMA,
//            ELU epilogue) writing the layer output.
// Layer output ping-pongs g_hx <-> g_h (blocks must not clobber their input).
// smem: As/Bs double buffers (73728 B) aliased by hs/es in phase 2; +2304 B.
// ===========================================================================
#define F_KC   64
#define F_NS   (HID / F_KC)    // 8
#define F_STR  72              // As/Bs/hs stride (288 B, 16B-aligned rows)
#define F_BUF  (64 * F_STR * 4)            // 18432 per tile
#define F_MISC (4 * F_BUF)                 // 73728
#define K24_SMEM (F_MISC + 2304)           // 76032

__global__ __launch_bounds__(256) void k24_layer(
    int layer, const int* __restrict__ adj, const float* __restrict__ ag)
{
    extern __shared__ __align__(16) char smem[];
    const int head = blockIdx.x;
    const int b    = blockIdx.y;
    const int tid  = threadIdx.x;
    const int lane = tid & 31;
    const int wid  = tid >> 5;
    const int wm   = wid & 3;      // 4 warps along M (16 rows)
    const int wn   = wid >> 2;     // 2 warps along N (32 cols)
    const uint32_t sbase = smem_u32(smem);

    const float* hin  = (layer & 1) ? g_h  : g_hx;
    float*       hout = (layer & 1) ? g_hx : g_h;
    const float* hx_b = hin + (size_t)b * NN * HID;
    const float* Wl   = g_Wr + ((size_t)layer * HEADS + head) * HID * FOUT;
    const float* a_l  = ag + (size_t)layer * HEADS * 2 * FOUT + head * 2 * FOUT;

    float* asv = (float*)(smem + F_MISC);          // 128
    float* f1  = asv + 128;                        // 64
    float* f2  = f1 + 64;                          // 64
    float* ps  = f2 + 64;                          // 4*64
    float* rsv = ps + 256;                         // 64

    if (tid < 2 * FOUT) asv[tid] = a_l[tid];
    // zero A pad rows 62,63 in both buffers (never written by cp.async)
    for (int idx = tid; idx < 2 * 2 * F_STR; idx += 256) {
        int p = idx / (2 * F_STR), rem = idx % (2 * F_STR);
        ((float*)(smem + p * 2 * F_BUF))[(62 + rem / F_STR) * F_STR + rem % F_STR] = 0.f;
    }

    auto issue_stage = [&](int s) {
        const int p = s & 1;
        const uint32_t Ad = sbase + p * 2 * F_BUF;
        const uint32_t Bd = Ad + F_BUF;
        // A: 62 rows x 16 float4 (cols s*64..s*64+63 of hx[b])
        for (int idx = tid; idx < NN * 16; idx += 256) {
            int r = idx >> 4, c4 = idx & 15;
            cp_async16(Ad + (r * F_STR + c4 * 4) * 4,
                       hx_b + (size_t)r * HID + s * F_KC + c4 * 4);
        }
        // B: 64 rows (k) x 16 float4 (W[k][0..63], contiguous)
#pragma unroll
        for (int i = 0; i < 4; i++) {
            int idx = tid + i * 256;
            int k = idx >> 4, c4 = idx & 15;
            cp_async16(Bd + (k * F_STR + c4 * 4) * 4,
                       Wl + (size_t)(s * F_KC + k) * FOUT + c4 * 4);
        }
    };

    float acc[4][4];
#pragma unroll
    for (int nt = 0; nt < 4; nt++)
#pragma unroll
        for (int q = 0; q < 4; q++) acc[nt][q] = 0.f;

    issue_stage(0);
    cp_commit();

#pragma unroll 1
    for (int s = 0; s < F_NS; s++) {
        if (s + 1 < F_NS) { issue_stage(s + 1); cp_commit(); cp_wait<1>(); }
        else              { cp_commit(); cp_wait<0>(); }
        __syncthreads();

        const float* As = (const float*)(smem + (s & 1) * 2 * F_BUF);
        const float* Bs = As + 64 * F_STR;
        const int r = wm * 16 + (lane >> 2);

#pragma unroll
        for (int kb = 0; kb < F_KC; kb += 8) {
            const int k = kb + (lane & 3);
            uint32_t a[4];
            a[0] = __float_as_uint(As[r * F_STR + k]);
            a[1] = __float_as_uint(As[(r + 8) * F_STR + k]);
            a[2] = __float_as_uint(As[r * F_STR + k + 4]);
            a[3] = __float_as_uint(As[(r + 8) * F_STR + k + 4]);
#pragma unroll
            for (int nt = 0; nt < 4; nt++) {
                const int c = wn * 32 + nt * 8 + (lane >> 2);
                uint32_t bb[2];
                bb[0] = __float_as_uint(Bs[k * F_STR + c]);
                bb[1] = __float_as_uint(Bs[(k + 4) * F_STR + c]);
                mma_tf32(acc[nt], a, bb);
            }
        }
        __syncthreads();   // buffer s&1 reusable for stage s+2
    }

    // ---- phase 2: attention. hs aliases buf0-A, es aliases buf0-B.
    float* hs = (float*)(smem);             // [64][F_STR]
    float* es = (float*)(smem + F_BUF);     // [64][68]

    // write h tile (raw fp32 accumulators; pad rows are 0 from zeroed A pads)
    {
        const int i0 = wm * 16 + (lane >> 2);
#pragma unroll
        for (int nt = 0; nt < 4; nt++) {
            int c = wn * 32 + nt * 8 + 2 * (lane & 3);
            *(float2*)&hs[i0 * F_STR + c]       = make_float2(acc[nt][0], acc[nt][1]);
            *(float2*)&hs[(i0 + 8) * F_STR + c] = make_float2(acc[nt][2], acc[nt][3]);
        }
    }
    __syncthreads();

    // f1/f2: 4 threads per node, quad shfl reduce
    {
        int node = tid >> 2, t = tid & 3;
        float s1 = 0.f, s2 = 0.f;
#pragma unroll
        for (int dd = 0; dd < 16; dd++) {
            int d = t * 16 + dd;
            float v = hs[node * F_STR + d];
            s1 += v * asv[d];
            s2 += v * asv[FOUT + d];
        }
        s1 += __shfl_xor_sync(0xffffffffu, s1, 1);
        s1 += __shfl_xor_sync(0xffffffffu, s1, 2);
        s2 += __shfl_xor_sync(0xffffffffu, s2, 1);
        s2 += __shfl_xor_sync(0xffffffffu, s2, 2);
        if (t == 0) { f1[node] = s1; f2[node] = s2; }
    }
    __syncthreads();

    // es[i][j] = tf32r(exp(leaky(f2[i]+f1[j]))) masked; pads = 0
    const int* adjb = adj + (size_t)b * NN * NN;
    for (int idx = tid; idx < 64 * 64; idx += 256) {
        int i = idx >> 6, j = idx & 63;
        float e = 0.f;
        if (i < NN && j < NN && adjb[i * NN + j] > 0) {
            float v = f2[i] + f1[j];
            v = v > 0.f ? v : 0.2f * v;
            e = tf32r(__expf(v));
        }
        es[i * 68 + j] = e;
    }
    __syncthreads();

    // column sums over i (softmax axis), 4 threads per column
    {
        int j = tid & 63, q = tid >> 6;
        float s = 0.f;
#pragma unroll
        for (int ii = 0; ii < 16; ii++) s += es[(q + ii * 4) * 68 + j];
        ps[q * 64 + j] = s;
    }
    __syncthreads();
    if (tid < 64) {
        float s = ps[tid] + ps[64 + tid] + ps[128 + tid] + ps[192 + tid];
        rsv[tid] = (s > 0.f) ? 1.f / s : 0.f;
    }
    __syncthreads();

    // fold 1/colsum[j] into hs row j, round to tf32
    for (int idx = tid; idx < 64 * 16; idx += 256) {
        int j = idx >> 4, d4 = idx & 15;
        float rs = rsv[j];
        float4 v = *(float4*)&hs[j * F_STR + d4 * 4];
        v.x = tf32r(v.x * rs); v.y = tf32r(v.y * rs);
        v.z = tf32r(v.z * rs); v.w = tf32r(v.w * rs);
        *(float4*)&hs[j * F_STR + d4 * 4] = v;
    }
    __syncthreads();

    // tensor-core aggregation D = es @ hs, then ELU + store
    {
        float acd[4][4];
#pragma unroll
        for (int nt = 0; nt < 4; nt++)
#pragma unroll
            for (int q = 0; q < 4; q++) acd[nt][q] = 0.f;

        const int r = wm * 16 + (lane >> 2);
#pragma unroll
        for (int kb = 0; kb < 64; kb += 8) {
            const int k = kb + (lane & 3);
            uint32_t a[4];
            a[0] = __float_as_uint(es[r * 68 + k]);
            a[1] = __float_as_uint(es[(r + 8) * 68 + k]);
            a[2] = __float_as_uint(es[r * 68 + k + 4]);
            a[3] = __float_as_uint(es[(r + 8) * 68 + k + 4]);
#pragma unroll
            for (int nt = 0; nt < 4; nt++) {
                const int c = wn * 32 + nt * 8 + (lane >> 2);
                uint32_t bb[2];
                bb[0] = __float_as_uint(hs[k * F_STR + c]);
                bb[1] = __float_as_uint(hs[(k + 4) * F_STR + c]);
                mma_tf32(acd[nt], a, bb);
            }
        }

        const int i0 = wm * 16 + (lane >> 2);   // <= 55, always valid
        const int i1 = i0 + 8;                  // may hit pad rows 62,63
        float* ob = hout + (size_t)b * NN * HID + head * FOUT;
#pragma unroll
        for (int nt = 0; nt < 4; nt++) {
            int c = wn * 32 + nt * 8 + 2 * (lane & 3);
            float v0 = acd[nt][0], v1 = acd[nt][1];
            v0 = v0 > 0.f ? v0 : expm1f(v0);
            v1 = v1 > 0.f ? v1 : expm1f(v1);
            *(float2*)(ob + (size_t)i0 * HID + c) =
                make_float2(tf32r(v0), tf32r(v1));
            if (i1 < NN) {
                float v2 = acd[nt][2], v3 = acd[nt][3];
                v2 = v2 > 0.f ? v2 : expm1f(v2);
                v3 = v3 > 0.f ? v3 : expm1f(v3);
                *(float2*)(ob + (size_t)i1 * HID + c) =
                    make_float2(tf32r(v2), tf32r(v3));
            }
        }
    }
}

// ===========================================================================
// K5: pool + output head + log_softmax (reads g_h = layer-2 output)
// ===========================================================================
__global__ __launch_bounds__(512) void k5_out(
    const float* __restrict__ Wout, const float* __restrict__ bout,
    float* __restrict__ out)
{
    int b = blockIdx.x, tid = threadIdx.x;
    int lane = tid & 31, wid = tid >> 5;
    const float* hb = &g_h[(size_t)b * NN * HID];
    float s = 0.f;
    for (int n = 0; n < NN; n++) s += hb[(size_t)n * HID + tid];

    float v0 = s * Wout[tid * 3 + 0];
    float v1 = s * Wout[tid * 3 + 1];
    float v2 = s * Wout[tid * 3 + 2];
#pragma unroll
    for (int off = 16; off > 0; off >>= 1) {
        v0 += __shfl_down_sync(0xffffffffu, v0, off);
        v1 += __shfl_down_sync(0xffffffffu, v1, off);
        v2 += __shfl_down_sync(0xffffffffu, v2, off);
    }
    __shared__ float red[3][16];
    if (lane == 0) { red[0][wid] = v0; red[1][wid] = v1; red[2][wid] = v2; }
    __syncthreads();
    if (tid == 0) {
        float lg[3];
#pragma unroll
        for (int c = 0; c < 3; c++) {
            float t = 0.f;
#pragma unroll
            for (int w = 0; w < 16; w++) t += red[c][w];
            lg[c] = t + bout[c];
        }
        float m = fmaxf(lg[0], fmaxf(lg[1], lg[2]));
        float sum = expf(lg[0] - m) + expf(lg[1] - m) + expf(lg[2] - m);
        float lse = logf(sum) + m;
        out[b * 3 + 0] = lg[0] - lse;
        out[b * 3 + 1] = lg[1] - lse;
        out[b * 3 + 2] = lg[2] - lse;
    }
}

// ===========================================================================
extern "C" void kernel_launch(void* const* d_in, const int* in_sizes, int n_in,
                              void* d_out, int out_size)
{
    const float* x     = (const float*)d_in[0];
    const int*   adj   = (const int*)  d_in[1];
    const float* gamma = (const float*)d_in[2];
    const float* beta  = (const float*)d_in[3];
    const float* mean  = (const float*)d_in[4];
    const float* var   = (const float*)d_in[5];
    const float* Wm    = (const float*)d_in[6];
    const float* bm    = (const float*)d_in[7];
    const float* Wg    = (const float*)d_in[8];
    const float* ag    = (const float*)d_in[9];
    const float* Wo    = (const float*)d_in[10];
    const float* bo    = (const float*)d_in[11];
    float* out = (float*)d_out;

    cudaFuncSetAttribute(k1_mma,    cudaFuncAttributeMaxDynamicSharedMemorySize, K1_SMEM);
    cudaFuncSetAttribute(k24_layer, cudaFuncAttributeMaxDynamicSharedMemorySize, K24_SMEM);

    k0_round_w<<<(3 * HEADS * HID * FOUT + 1023) / 1024, 1024>>>(Wg);
    k0_round_wm<<<(FIN * HID + 1023) / 1024, 1024>>>(Wm);
    k0_colsum_wm<<<1, HID>>>();
    k0_round_x<<<(int)(((size_t)NROWS * FIN) / 1024), 256>>>(x);

    k1_mma<<<dim3(HID / TN, NROWS / TM), 256, K1_SMEM>>>(gamma, beta, mean, var, bm);

    for (int l = 0; l < 3; l++) {
        k24_layer<<<dim3(HEADS, BB), 256, K24_SMEM>>>(l, adj, ag);
    }

    k5_out<<<BB, 512>>>(Wo, bo, out);
}

// round 11
// speedup vs baseline: 1.2058x; 1.2058x over previous
#include <cuda_runtime.h>
#include <math.h>
#include <cstdint>

#define BB    2048
#define NN    62
#define FIN   128
#define HID   512
#define HEADS 8
#define FOUT  64
#define NROWS (BB * NN)   // 126976

__device__ float g_hx[(size_t)NROWS * HID];
__device__ float g_h [(size_t)NROWS * HID];
__device__ float g_Wr[(size_t)3 * HEADS * HID * FOUT];
__device__ float g_Wmr[FIN * HID];
__device__ float g_cs[HID];

// ===========================================================================
// helpers
// ===========================================================================
__device__ __forceinline__ uint32_t smem_u32(const void* p) {
    uint32_t a;
    asm("{ .reg .u64 t; cvta.to.shared.u64 t, %1; cvt.u32.u64 %0, t; }"
        : "=r"(a) : "l"(p));
    return a;
}
__device__ __forceinline__ float tf32r(float x) {
    uint32_t u;
    asm("cvt.rna.tf32.f32 %0, %1;" : "=r"(u) : "f"(x));
    return __uint_as_float(u);
}
__device__ __forceinline__ uint32_t tf32u(float x) {
    uint32_t u;
    asm("cvt.rna.tf32.f32 %0, %1;" : "=r"(u) : "f"(x));
    return u;
}
__device__ __forceinline__ void cp_async16(uint32_t dst, const void* src) {
    asm volatile("cp.async.cg.shared.global [%0], [%1], 16;"
                 :: "r"(dst), "l"(src) : "memory");
}
__device__ __forceinline__ void cp_commit() {
    asm volatile("cp.async.commit_group;" ::: "memory");
}
template <int N>
__device__ __forceinline__ void cp_wait() {
    asm volatile("cp.async.wait_group %0;" :: "n"(N) : "memory");
}
__device__ __forceinline__ void mma_tf32(float* c, const uint32_t* a, const uint32_t* b) {
    asm volatile(
        "mma.sync.aligned.m16n8k8.row.col.f32.tf32.tf32.f32 "
        "{%0,%1,%2,%3}, {%4,%5,%6,%7}, {%8,%9}, {%0,%1,%2,%3};"
        : "+f"(c[0]), "+f"(c[1]), "+f"(c[2]), "+f"(c[3])
        : "r"(a[0]), "r"(a[1]), "r"(a[2]), "r"(a[3]), "r"(b[0]), "r"(b[1]));
}

// ===========================================================================
// K0 kernels: tf32 rounding of weight operands (x handled in-kernel by K1)
// ===========================================================================
__global__ void k0_round_w(const float* __restrict__ Wg) {
    int i = blockIdx.x * 1024 + threadIdx.x;
    if (i < 3 * HEADS * HID * FOUT) g_Wr[i] = tf32r(Wg[i]);
}
__global__ void k0_round_wm(const float* __restrict__ Wm) {
    int i = blockIdx.x * 1024 + threadIdx.x;
    if (i < FIN * HID) g_Wmr[i] = tf32r(Wm[i]);
}
__global__ void k0_colsum_wm() {
    int c = threadIdx.x;
    float s = 0.f;
    for (int k = 0; k < FIN; k++) s += g_Wmr[k * HID + c];
    g_cs[c] = s;
}

// ===========================================================================
// shared GEMM tile config (K1M / K2) — NBUF=3 -> 107.5 KB -> 2 CTAs/SM
// ===========================================================================
#define TM 128
#define TN 128
#define KC 32
#define NBUF 3
#define A_STRIDE 36
#define B_STRIDE 136
#define A_BYTES (TM * A_STRIDE * 4)
#define B_BYTES (KC * B_STRIDE * 4)
#define STAGE_BYTES (A_BYTES + B_BYTES)    // 35840
#define K2_SMEM (NBUF * STAGE_BYTES)       // 107520

__device__ __forceinline__ int slot3(int s) { return s - (s / 3) * 3; }

// ===========================================================================
// K1M (tf32 mma): h_x = s_row*(x @ Wm) + t_row*colsum(Wm) + b
// A = raw x; tf32 RNA applied to a-frags after LDS.
// ===========================================================================
__global__ __launch_bounds__(256, 2) void k1_mma(
    const float* __restrict__ x,
    const float* __restrict__ gamma, const float* __restrict__ beta,
    const float* __restrict__ mean,  const float* __restrict__ var,
    const float* __restrict__ bm)
{
    extern __shared__ __align__(16) char smem[];
    const int NS_K = FIN / KC;   // 4
    const int tid  = threadIdx.x;
    const int lane = tid & 31;
    const int wid  = tid >> 5;
    const int wm   = wid & 3;
    const int wn   = wid >> 2;
    const int n0   = blockIdx.x * TN;
    const int row0 = blockIdx.y * TM;
    const uint32_t sbase = smem_u32(smem);

    auto issue_stage = [&](int s) {
        const int p = slot3(s);
        const float* Ag = x + (size_t)row0 * FIN + s * KC;
        const uint32_t Ad = sbase + p * STAGE_BYTES;
#pragma unroll
        for (int i = 0; i < 4; i++) {
            int idx = tid + i * 256;
            int r = idx >> 3, k4 = idx & 7;
            cp_async16(Ad + r * (A_STRIDE * 4) + k4 * 16,
                       Ag + (size_t)r * FIN + k4 * 4);
        }
        const uint32_t Bd = sbase + p * STAGE_BYTES + A_BYTES;
#pragma unroll
        for (int i = 0; i < 4; i++) {
            int idx = tid + i * 256;
            int k = idx >> 5, n4 = idx & 31;
            cp_async16(Bd + k * (B_STRIDE * 4) + n4 * 16,
                       g_Wmr + (size_t)(s * KC + k) * HID + n0 + n4 * 4);
        }
    };

    float acc[2][8][4];
#pragma unroll
    for (int mt = 0; mt < 2; mt++)
#pragma unroll
        for (int nt = 0; nt < 8; nt++)
#pragma unroll
            for (int q = 0; q < 4; q++) acc[mt][nt][q] = 0.f;

#pragma unroll
    for (int s = 0; s < NBUF - 1; s++) { issue_stage(s); cp_commit(); }

#pragma unroll 1
    for (int s = 0; s < NS_K; s++) {
        if (s < NS_K - 1) cp_wait<1>();
        else              cp_wait<0>();
        __syncthreads();
        if (s + NBUF - 1 < NS_K) issue_stage(s + NBUF - 1);
        cp_commit();

        const float* As = (const float*)(smem + slot3(s) * STAGE_BYTES);
        const float* Bs = As + TM * A_STRIDE;

#pragma unroll
        for (int ks = 0; ks < KC / 8; ks++) {
            const int kb = ks * 8;
            uint32_t a[2][4], b[8][2];
#pragma unroll
            for (int mt = 0; mt < 2; mt++) {
                int r = wm * 32 + mt * 16 + (lane >> 2);
                int k = kb + (lane & 3);
                a[mt][0] = tf32u(As[r * A_STRIDE + k]);
                a[mt][1] = tf32u(As[(r + 8) * A_STRIDE + k]);
                a[mt][2] = tf32u(As[r * A_STRIDE + k + 4]);
                a[mt][3] = tf32u(As[(r + 8) * A_STRIDE + k + 4]);
            }
#pragma unroll
            for (int nt = 0; nt < 8; nt++) {
                int c = wn * 64 + nt * 8 + (lane >> 2);
                int k = kb + (lane & 3);
                b[nt][0] = __float_as_uint(Bs[k * B_STRIDE + c]);
                b[nt][1] = __float_as_uint(Bs[(k + 4) * B_STRIDE + c]);
            }
#pragma unroll
            for (int mt = 0; mt < 2; mt++)
#pragma unroll
                for (int nt = 0; nt < 8; nt++)
                    mma_tf32(acc[mt][nt], a[mt], b[nt]);
        }
    }

    const int rbase = wm * 32 + (lane >> 2);
    float sv[4], tv[4];
#pragma unroll
    for (int q = 0; q < 4; q++) {
        int r = row0 + rbase + q * 8;
        int n = r % NN;
        float sc = gamma[n] * rsqrtf(var[n] + 1e-5f);
        sv[q] = sc;
        tv[q] = beta[n] - mean[n] * sc;
    }
#pragma unroll
    for (int mt = 0; mt < 2; mt++) {
        int r = row0 + rbase + mt * 16;
#pragma unroll
        for (int nt = 0; nt < 8; nt++) {
            int c = n0 + wn * 64 + nt * 8 + 2 * (lane & 3);
            float cs0 = g_cs[c], cs1 = g_cs[c + 1];
            float b0 = bm[c], b1 = bm[c + 1];
            int q0 = mt * 2, q1 = mt * 2 + 1;
            *(float2*)&g_hx[(size_t)r * HID + c] = make_float2(
                tf32r(sv[q0] * acc[mt][nt][0] + tv[q0] * cs0 + b0),
                tf32r(sv[q0] * acc[mt][nt][1] + tv[q0] * cs1 + b1));
            *(float2*)&g_hx[(size_t)(r + 8) * HID + c] = make_float2(
                tf32r(sv[q1] * acc[mt][nt][2] + tv[q1] * cs0 + b0),
                tf32r(sv[q1] * acc[mt][nt][3] + tv[q1] * cs1 + b1));
        }
    }
}

// ===========================================================================
// K2 (tf32 mma): g_h = g_hx @ W_gat[l]
// ===========================================================================
__global__ __launch_bounds__(256, 2) void k2_mma(int layer)
{
    extern __shared__ __align__(16) char smem[];
    const int NS_K = HID / KC;   // 16
    const int tid  = threadIdx.x;
    const int lane = tid & 31;
    const int wid  = tid >> 5;
    const int wm   = wid & 3;
    const int wn   = wid >> 2;
    const int n0   = blockIdx.x * TN;
    const int row0 = blockIdx.y * TM;
    const uint32_t sbase = smem_u32(smem);
    const float* Wl = g_Wr + (size_t)layer * HEADS * HID * FOUT;
    const float* Wb = Wl + (size_t)(n0 >> 6) * HID * FOUT;

    auto issue_stage = [&](int s) {
        const int p = slot3(s);
        const float* Ag = g_hx + (size_t)row0 * HID + s * KC;
        const uint32_t Ad = sbase + p * STAGE_BYTES;
#pragma unroll
        for (int i = 0; i < 4; i++) {
            int idx = tid + i * 256;
            int r = idx >> 3, k4 = idx & 7;
            cp_async16(Ad + r * (A_STRIDE * 4) + k4 * 16,
                       Ag + (size_t)r * HID + k4 * 4);
        }
        const uint32_t Bd = sbase + p * STAGE_BYTES + A_BYTES;
#pragma unroll
        for (int i = 0; i < 4; i++) {
            int idx = tid + i * 256;
            int k = idx >> 5, n4 = idx & 31;
            int n = n4 * 4;
            const float* sp = Wb + (size_t)(n >> 6) * HID * FOUT
                                 + (size_t)(s * KC + k) * FOUT + (n & 63);
            cp_async16(Bd + k * (B_STRIDE * 4) + n4 * 16, sp);
        }
    };

    float acc[2][8][4];
#pragma unroll
    for (int mt = 0; mt < 2; mt++)
#pragma unroll
        for (int nt = 0; nt < 8; nt++)
#pragma unroll
            for (int q = 0; q < 4; q++) acc[mt][nt][q] = 0.f;

#pragma unroll
    for (int s = 0; s < NBUF - 1; s++) { issue_stage(s); cp_commit(); }

#pragma unroll 1
    for (int s = 0; s < NS_K; s++) {
        if (s < NS_K - 1) cp_wait<1>();
        else              cp_wait<0>();
        __syncthreads();
        if (s + NBUF - 1 < NS_K) issue_stage(s + NBUF - 1);
        cp_commit();

        const float* As = (const float*)(smem + slot3(s) * STAGE_BYTES);
        const float* Bs = As + TM * A_STRIDE;

#pragma unroll
        for (int ks = 0; ks < KC / 8; ks++) {
            const int kb = ks * 8;
            uint32_t a[2][4], b[8][2];
#pragma unroll
            for (int mt = 0; mt < 2; mt++) {
                int r = wm * 32 + mt * 16 + (lane >> 2);
                int k = kb + (lane & 3);
                a[mt][0] = __float_as_uint(As[r * A_STRIDE + k]);
                a[mt][1] = __float_as_uint(As[(r + 8) * A_STRIDE + k]);
                a[mt][2] = __float_as_uint(As[r * A_STRIDE + k + 4]);
                a[mt][3] = __float_as_uint(As[(r + 8) * A_STRIDE + k + 4]);
            }
#pragma unroll
            for (int nt = 0; nt < 8; nt++) {
                int c = wn * 64 + nt * 8 + (lane >> 2);
                int k = kb + (lane & 3);
                b[nt][0] = __float_as_uint(Bs[k * B_STRIDE + c]);
                b[nt][1] = __float_as_uint(Bs[(k + 4) * B_STRIDE + c]);
            }
#pragma unroll
            for (int mt = 0; mt < 2; mt++)
#pragma unroll
                for (int nt = 0; nt < 8; nt++)
                    mma_tf32(acc[mt][nt], a[mt], b[nt]);
        }
    }

#pragma unroll
    for (int mt = 0; mt < 2; mt++) {
        int r = row0 + wm * 32 + mt * 16 + (lane >> 2);
#pragma unroll
        for (int nt = 0; nt < 8; nt++) {
            int c = n0 + wn * 64 + nt * 8 + 2 * (lane & 3);
            *(float2*)&g_h[(size_t)r * HID + c] =
                make_float2(acc[mt][nt][0], acc[mt][nt][1]);
            *(float2*)&g_h[(size_t)(r + 8) * HID + c] =
                make_float2(acc[mt][nt][2], acc[mt][nt][3]);
        }
    }
}

// ===========================================================================
// K4: per-(batch, head) attention — round-8 version (tensor-core aggregation)
// ===========================================================================
#define HS_STR 72
#define ES_STR 68

__global__ __launch_bounds__(256) void k4_attn(
    const int* __restrict__ adj, const float* __restrict__ a_l)
{
    __shared__ float hs[64][HS_STR];
    __shared__ float es[64][ES_STR];
    __shared__ float asv[2 * FOUT];
    __shared__ float f1[64], f2[64];
    __shared__ float ps[4][64];
    __shared__ float rsv[64];

    const int b    = blockIdx.x;
    const int head = blockIdx.y;
    const int tid  = threadIdx.x;
    const int lane = tid & 31;
    const int wid  = tid >> 5;

    const float* hbase = &g_h[(size_t)b * NN * HID + head * FOUT];
    for (int idx = tid; idx < 64 * 16; idx += 256) {
        int j = idx >> 4, d4 = idx & 15;
        float4 v = (j < NN) ? *(const float4*)(hbase + (size_t)j * HID + d4 * 4)
                            : make_float4(0.f, 0.f, 0.f, 0.f);
        *(float4*)&hs[j][d4 * 4] = v;
    }
    if (tid < 2 * FOUT) asv[tid] = a_l[head * 2 * FOUT + tid];   // per-head vec (round-10 bug fixed)
    __syncthreads();

    {
        int node = tid >> 2, t = tid & 3;
        float s1 = 0.f, s2 = 0.f;
#pragma unroll
        for (int dd = 0; dd < 16; dd++) {
            int d = t * 16 + dd;
            float v = hs[node][d];
            s1 += v * asv[d];
            s2 += v * asv[FOUT + d];
        }
        s1 += __shfl_xor_sync(0xffffffffu, s1, 1);
        s1 += __shfl_xor_sync(0xffffffffu, s1, 2);
        s2 += __shfl_xor_sync(0xffffffffu, s2, 1);
        s2 += __shfl_xor_sync(0xffffffffu, s2, 2);
        if (t == 0) { f1[node] = s1; f2[node] = s2; }
    }
    __syncthreads();

    const int* adjb = adj + (size_t)b * NN * NN;
    for (int idx = tid; idx < 64 * 64; idx += 256) {
        int i = idx >> 6, j = idx & 63;
        float e = 0.f;
        if (i < NN && j < NN && adjb[i * NN + j] > 0) {
            float v = f2[i] + f1[j];
            v = v > 0.f ? v : 0.2f * v;
            e = tf32r(__expf(v));
        }
        es[i][j] = e;
    }
    __syncthreads();

    {
        int j = tid & 63, q = tid >> 6;
        float s = 0.f;
#pragma unroll
        for (int ii = 0; ii < 16; ii++) s += es[q + ii * 4][j];
        ps[q][j] = s;
    }
    __syncthreads();
    if (tid < 64) {
        float s = ps[0][tid] + ps[1][tid] + ps[2][tid] + ps[3][tid];
        rsv[tid] = (s > 0.f) ? 1.f / s : 0.f;
    }
    __syncthreads();

    for (int idx = tid; idx < 64 * 16; idx += 256) {
        int j = idx >> 4, d4 = idx & 15;
        float rs = rsv[j];
        float4 v = *(float4*)&hs[j][d4 * 4];
        v.x = tf32r(v.x * rs); v.y = tf32r(v.y * rs);
        v.z = tf32r(v.z * rs); v.w = tf32r(v.w * rs);
        *(float4*)&hs[j][d4 * 4] = v;
    }
    __syncthreads();

    {
        const int wm = wid & 3, wn = wid >> 2;
        float acc[4][4];
#pragma unroll
        for (int nt = 0; nt < 4; nt++)
#pragma unroll
            for (int q = 0; q < 4; q++) acc[nt][q] = 0.f;

        const int r = wm * 16 + (lane >> 2);
#pragma unroll
        for (int kb = 0; kb < 64; kb += 8) {
            const int k = kb + (lane & 3);
            uint32_t a[4];
            a[0] = __float_as_uint(es[r][k]);
            a[1] = __float_as_uint(es[r + 8][k]);
            a[2] = __float_as_uint(es[r][k + 4]);
            a[3] = __float_as_uint(es[r + 8][k + 4]);
#pragma unroll
            for (int nt = 0; nt < 4; nt++) {
                const int c = wn * 32 + nt * 8 + (lane >> 2);
                uint32_t bb[2];
                bb[0] = __float_as_uint(hs[k][c]);
                bb[1] = __float_as_uint(hs[k + 4][c]);
                mma_tf32(acc[nt], a, bb);
            }
        }

        const int i0 = wm * 16 + (lane >> 2);
        const int i1 = i0 + 8;
        float* ob = &g_hx[(size_t)b * NN * HID + head * FOUT];
#pragma unroll
        for (int nt = 0; nt < 4; nt++) {
            int c = wn * 32 + nt * 8 + 2 * (lane & 3);
            float v0 = acc[nt][0], v1 = acc[nt][1];
            v0 = v0 > 0.f ? v0 : expm1f(v0);
            v1 = v1 > 0.f ? v1 : expm1f(v1);
            *(float2*)(ob + (size_t)i0 * HID + c) =
                make_float2(tf32r(v0), tf32r(v1));
            if (i1 < NN) {
                float v2 = acc[nt][2], v3 = acc[nt][3];
                v2 = v2 > 0.f ? v2 : expm1f(v2);
                v3 = v3 > 0.f ? v3 : expm1f(v3);
                *(float2*)(ob + (size_t)i1 * HID + c) =
                    make_float2(tf32r(v2), tf32r(v3));
            }
        }
    }
}

// ===========================================================================
// K5: pool + output head + log_softmax
// ===========================================================================
__global__ __launch_bounds__(512) void k5_out(
    const float* __restrict__ Wout, const float* __restrict__ bout,
    float* __restrict__ out)
{
    int b = blockIdx.x, tid = threadIdx.x;
    int lane = tid & 31, wid = tid >> 5;
    const float* hb = &g_hx[(size_t)b * NN * HID];
    float s = 0.f;
    for (int n = 0; n < NN; n++) s += hb[(size_t)n * HID + tid];

    float v0 = s * Wout[tid * 3 + 0];
    float v1 = s * Wout[tid * 3 + 1];
    float v2 = s * Wout[tid * 3 + 2];
#pragma unroll
    for (int off = 16; off > 0; off >>= 1) {
        v0 += __shfl_down_sync(0xffffffffu, v0, off);
        v1 += __shfl_down_sync(0xffffffffu, v1, off);
        v2 += __shfl_down_sync(0xffffffffu, v2, off);
    }
    __shared__ float red[3][16];
    if (lane == 0) { red[0][wid] = v0; red[1][wid] = v1; red[2][wid] = v2; }
    __syncthreads();
    if (tid == 0) {
        float lg[3];
#pragma unroll
        for (int c = 0; c < 3; c++) {
            float t = 0.f;
#pragma unroll
            for (int w = 0; w < 16; w++) t += red[c][w];
            lg[c] = t + bout[c];
        }
        float m = fmaxf(lg[0], fmaxf(lg[1], lg[2]));
        float sum = expf(lg[0] - m) + expf(lg[1] - m) + expf(lg[2] - m);
        float lse = logf(sum) + m;
        out[b * 3 + 0] = lg[0] - lse;
        out[b * 3 + 1] = lg[1] - lse;
        out[b * 3 + 2] = lg[2] - lse;
    }
}

// ===========================================================================
extern "C" void kernel_launch(void* const* d_in, const int* in_sizes, int n_in,
                              void* d_out, int out_size)
{
    const float* x     = (const float*)d_in[0];
    const int*   adj   = (const int*)  d_in[1];
    const float* gamma = (const float*)d_in[2];
    const float* beta  = (const float*)d_in[3];
    const float* mean  = (const float*)d_in[4];
    const float* var   = (const float*)d_in[5];
    const float* Wm    = (const float*)d_in[6];
    const float* bm    = (const float*)d_in[7];
    const float* Wg    = (const float*)d_in[8];
    const float* ag    = (const float*)d_in[9];
    const float* Wo    = (const float*)d_in[10];
    const float* bo    = (const float*)d_in[11];
    float* out = (float*)d_out;

    cudaFuncSetAttribute(k2_mma, cudaFuncAttributeMaxDynamicSharedMemorySize, K2_SMEM);
    cudaFuncSetAttribute(k1_mma, cudaFuncAttributeMaxDynamicSharedMemorySize, K2_SMEM);

    k0_round_w<<<(3 * HEADS * HID * FOUT + 1023) / 1024, 1024>>>(Wg);
    k0_round_wm<<<(FIN * HID + 1023) / 1024, 1024>>>(Wm);
    k0_colsum_wm<<<1, HID>>>();

    k1_mma<<<dim3(HID / TN, NROWS / TM), 256, K2_SMEM>>>(x, gamma, beta, mean, var, bm);

    for (int l = 0; l < 3; l++) {
        k2_mma<<<dim3(HID / TN, NROWS / TM), 256, K2_SMEM>>>(l);
        k4_attn<<<dim3(BB, HEADS), 256>>>(adj, ag + (size_t)l * HEADS * 2 * FOUT);
    }

    k5_out<<<BB, 512>>>(Wo, bo, out);
}

// round 12
// speedup vs baseline: 1.3330x; 1.1054x over previous
#include <cuda_runtime.h>
#include <math.h>
#include <cstdint>

#define BB    2048
#define NN    62
#define FIN   128
#define HID   512
#define HEADS 8
#define FOUT  64
#define NROWS (BB * NN)   // 126976

__device__ float g_hx[(size_t)NROWS * HID];
__device__ float g_h [(size_t)NROWS * HID];
__device__ float g_Wr[(size_t)3 * HEADS * HID * FOUT];
__device__ float g_Wmr[FIN * HID];
__device__ float g_cs[HID];

// ===========================================================================
// helpers
// ===========================================================================
__device__ __forceinline__ uint32_t smem_u32(const void* p) {
    uint32_t a;
    asm("{ .reg .u64 t; cvta.to.shared.u64 t, %1; cvt.u32.u64 %0, t; }"
        : "=r"(a) : "l"(p));
    return a;
}
__device__ __forceinline__ float tf32r(float x) {
    uint32_t u;
    asm("cvt.rna.tf32.f32 %0, %1;" : "=r"(u) : "f"(x));
    return __uint_as_float(u);
}
__device__ __forceinline__ uint32_t tf32u(float x) {
    uint32_t u;
    asm("cvt.rna.tf32.f32 %0, %1;" : "=r"(u) : "f"(x));
    return u;
}
__device__ __forceinline__ void cp_async16(uint32_t dst, const void* src) {
    asm volatile("cp.async.cg.shared.global [%0], [%1], 16;"
                 :: "r"(dst), "l"(src) : "memory");
}
__device__ __forceinline__ void cp_commit() {
    asm volatile("cp.async.commit_group;" ::: "memory");
}
template <int N>
__device__ __forceinline__ void cp_wait() {
    asm volatile("cp.async.wait_group %0;" :: "n"(N) : "memory");
}
__device__ __forceinline__ void mma_tf32(float* c, const uint32_t* a, const uint32_t* b) {
    asm volatile(
        "mma.sync.aligned.m16n8k8.row.col.f32.tf32.tf32.f32 "
        "{%0,%1,%2,%3}, {%4,%5,%6,%7}, {%8,%9}, {%0,%1,%2,%3};"
        : "+f"(c[0]), "+f"(c[1]), "+f"(c[2]), "+f"(c[3])
        : "r"(a[0]), "r"(a[1]), "r"(a[2]), "r"(a[3]), "r"(b[0]), "r"(b[1]));
}

// ===========================================================================
// K0 kernels: tf32 rounding of weight operands
// ===========================================================================
__global__ void k0_round_w(const float* __restrict__ Wg) {
    int i = blockIdx.x * 1024 + threadIdx.x;
    if (i < 3 * HEADS * HID * FOUT) g_Wr[i] = tf32r(Wg[i]);
}
__global__ void k0_round_wm(const float* __restrict__ Wm) {
    int i = blockIdx.x * 1024 + threadIdx.x;
    if (i < FIN * HID) g_Wmr[i] = tf32r(Wm[i]);
}
__global__ void k0_colsum_wm() {
    int c = threadIdx.x;
    float s = 0.f;
    for (int k = 0; k < FIN; k++) s += g_Wmr[k * HID + c];
    g_cs[c] = s;
}

// ===========================================================================
// shared GEMM tile config (K1M / K2) — NBUF=3 -> 107.5 KB -> 2 CTAs/SM
// ===========================================================================
#define TM 128
#define TN 128
#define KC 32
#define NBUF 3
#define A_STRIDE 36
#define B_STRIDE 136
#define A_BYTES (TM * A_STRIDE * 4)
#define B_BYTES (KC * B_STRIDE * 4)
#define STAGE_BYTES (A_BYTES + B_BYTES)    // 35840
#define K2_SMEM (NBUF * STAGE_BYTES)       // 107520

__device__ __forceinline__ int slot3(int s) { return s - (s / 3) * 3; }

// ===========================================================================
// K1M (tf32 mma): h_x = s_row*(x @ Wm) + t_row*colsum(Wm) + b
// ===========================================================================
__global__ __launch_bounds__(256, 2) void k1_mma(
    const float* __restrict__ x,
    const float* __restrict__ gamma, const float* __restrict__ beta,
    const float* __restrict__ mean,  const float* __restrict__ var,
    const float* __restrict__ bm)
{
    extern __shared__ __align__(16) char smem[];
    const int NS_K = FIN / KC;   // 4
    const int tid  = threadIdx.x;
    const int lane = tid & 31;
    const int wid  = tid >> 5;
    const int wm   = wid & 3;
    const int wn   = wid >> 2;
    const int n0   = blockIdx.x * TN;
    const int row0 = blockIdx.y * TM;
    const uint32_t sbase = smem_u32(smem);

    auto issue_stage = [&](int s) {
        const int p = slot3(s);
        const float* Ag = x + (size_t)row0 * FIN + s * KC;
        const uint32_t Ad = sbase + p * STAGE_BYTES;
#pragma unroll
        for (int i = 0; i < 4; i++) {
            int idx = tid + i * 256;
            int r = idx >> 3, k4 = idx & 7;
            cp_async16(Ad + r * (A_STRIDE * 4) + k4 * 16,
                       Ag + (size_t)r * FIN + k4 * 4);
        }
        const uint32_t Bd = sbase + p * STAGE_BYTES + A_BYTES;
#pragma unroll
        for (int i = 0; i < 4; i++) {
            int idx = tid + i * 256;
            int k = idx >> 5, n4 = idx & 31;
            cp_async16(Bd + k * (B_STRIDE * 4) + n4 * 16,
                       g_Wmr + (size_t)(s * KC + k) * HID + n0 + n4 * 4);
        }
    };

    float acc[2][8][4];
#pragma unroll
    for (int mt = 0; mt < 2; mt++)
#pragma unroll
        for (int nt = 0; nt < 8; nt++)
#pragma unroll
            for (int q = 0; q < 4; q++) acc[mt][nt][q] = 0.f;

#pragma unroll
    for (int s = 0; s < NBUF - 1; s++) { issue_stage(s); cp_commit(); }

#pragma unroll 1
    for (int s = 0; s < NS_K; s++) {
        if (s < NS_K - 1) cp_wait<1>();
        else              cp_wait<0>();
        __syncthreads();
        if (s + NBUF - 1 < NS_K) issue_stage(s + NBUF - 1);
        cp_commit();

        const float* As = (const float*)(smem + slot3(s) * STAGE_BYTES);
        const float* Bs = As + TM * A_STRIDE;

#pragma unroll
        for (int ks = 0; ks < KC / 8; ks++) {
            const int kb = ks * 8;
            uint32_t a[2][4], b[8][2];
#pragma unroll
            for (int mt = 0; mt < 2; mt++) {
                int r = wm * 32 + mt * 16 + (lane >> 2);
                int k = kb + (lane & 3);
                a[mt][0] = tf32u(As[r * A_STRIDE + k]);
                a[mt][1] = tf32u(As[(r + 8) * A_STRIDE + k]);
                a[mt][2] = tf32u(As[r * A_STRIDE + k + 4]);
                a[mt][3] = tf32u(As[(r + 8) * A_STRIDE + k + 4]);
            }
#pragma unroll
            for (int nt = 0; nt < 8; nt++) {
                int c = wn * 64 + nt * 8 + (lane >> 2);
                int k = kb + (lane & 3);
                b[nt][0] = __float_as_uint(Bs[k * B_STRIDE + c]);
                b[nt][1] = __float_as_uint(Bs[(k + 4) * B_STRIDE + c]);
            }
#pragma unroll
            for (int mt = 0; mt < 2; mt++)
#pragma unroll
                for (int nt = 0; nt < 8; nt++)
                    mma_tf32(acc[mt][nt], a[mt], b[nt]);
        }
    }

    const int rbase = wm * 32 + (lane >> 2);
    float sv[4], tv[4];
#pragma unroll
    for (int q = 0; q < 4; q++) {
        int r = row0 + rbase + q * 8;
        int n = r % NN;
        float sc = gamma[n] * rsqrtf(var[n] + 1e-5f);
        sv[q] = sc;
        tv[q] = beta[n] - mean[n] * sc;
    }
#pragma unroll
    for (int mt = 0; mt < 2; mt++) {
        int r = row0 + rbase + mt * 16;
#pragma unroll
        for (int nt = 0; nt < 8; nt++) {
            int c = n0 + wn * 64 + nt * 8 + 2 * (lane & 3);
            float cs0 = g_cs[c], cs1 = g_cs[c + 1];
            float b0 = bm[c], b1 = bm[c + 1];
            int q0 = mt * 2, q1 = mt * 2 + 1;
            *(float2*)&g_hx[(size_t)r * HID + c] = make_float2(
                tf32r(sv[q0] * acc[mt][nt][0] + tv[q0] * cs0 + b0),
                tf32r(sv[q0] * acc[mt][nt][1] + tv[q0] * cs1 + b1));
            *(float2*)&g_hx[(size_t)(r + 8) * HID + c] = make_float2(
                tf32r(sv[q1] * acc[mt][nt][2] + tv[q1] * cs0 + b0),
                tf32r(sv[q1] * acc[mt][nt][3] + tv[q1] * cs1 + b1));
        }
    }
}

// ===========================================================================
// K2 (tf32 mma): g_h = g_hx @ W_gat[l]
// ===========================================================================
__global__ __launch_bounds__(256, 2) void k2_mma(int layer)
{
    extern __shared__ __align__(16) char smem[];
    const int NS_K = HID / KC;   // 16
    const int tid  = threadIdx.x;
    const int lane = tid & 31;
    const int wid  = tid >> 5;
    const int wm   = wid & 3;
    const int wn   = wid >> 2;
    const int n0   = blockIdx.x * TN;
    const int row0 = blockIdx.y * TM;
    const uint32_t sbase = smem_u32(smem);
    const float* Wl = g_Wr + (size_t)layer * HEADS * HID * FOUT;
    const float* Wb = Wl + (size_t)(n0 >> 6) * HID * FOUT;

    auto issue_stage = [&](int s) {
        const int p = slot3(s);
        const float* Ag = g_hx + (size_t)row0 * HID + s * KC;
        const uint32_t Ad = sbase + p * STAGE_BYTES;
#pragma unroll
        for (int i = 0; i < 4; i++) {
            int idx = tid + i * 256;
            int r = idx >> 3, k4 = idx & 7;
            cp_async16(Ad + r * (A_STRIDE * 4) + k4 * 16,
                       Ag + (size_t)r * HID + k4 * 4);
        }
        const uint32_t Bd = sbase + p * STAGE_BYTES + A_BYTES;
#pragma unroll
        for (int i = 0; i < 4; i++) {
            int idx = tid + i * 256;
            int k = idx >> 5, n4 = idx & 31;
            int n = n4 * 4;
            const float* sp = Wb + (size_t)(n >> 6) * HID * FOUT
                                 + (size_t)(s * KC + k) * FOUT + (n & 63);
            cp_async16(Bd + k * (B_STRIDE * 4) + n4 * 16, sp);
        }
    };

    float acc[2][8][4];
#pragma unroll
    for (int mt = 0; mt < 2; mt++)
#pragma unroll
        for (int nt = 0; nt < 8; nt++)
#pragma unroll
            for (int q = 0; q < 4; q++) acc[mt][nt][q] = 0.f;

#pragma unroll
    for (int s = 0; s < NBUF - 1; s++) { issue_stage(s); cp_commit(); }

#pragma unroll 1
    for (int s = 0; s < NS_K; s++) {
        if (s < NS_K - 1) cp_wait<1>();
        else              cp_wait<0>();
        __syncthreads();
        if (s + NBUF - 1 < NS_K) issue_stage(s + NBUF - 1);
        cp_commit();

        const float* As = (const float*)(smem + slot3(s) * STAGE_BYTES);
        const float* Bs = As + TM * A_STRIDE;

#pragma unroll
        for (int ks = 0; ks < KC / 8; ks++) {
            const int kb = ks * 8;
            uint32_t a[2][4], b[8][2];
#pragma unroll
            for (int mt = 0; mt < 2; mt++) {
                int r = wm * 32 + mt * 16 + (lane >> 2);
                int k = kb + (lane & 3);
                a[mt][0] = __float_as_uint(As[r * A_STRIDE + k]);
                a[mt][1] = __float_as_uint(As[(r + 8) * A_STRIDE + k]);
                a[mt][2] = __float_as_uint(As[r * A_STRIDE + k + 4]);
                a[mt][3] = __float_as_uint(As[(r + 8) * A_STRIDE + k + 4]);
            }
#pragma unroll
            for (int nt = 0; nt < 8; nt++) {
                int c = wn * 64 + nt * 8 + (lane >> 2);
                int k = kb + (lane & 3);
                b[nt][0] = __float_as_uint(Bs[k * B_STRIDE + c]);
                b[nt][1] = __float_as_uint(Bs[(k + 4) * B_STRIDE + c]);
            }
#pragma unroll
            for (int mt = 0; mt < 2; mt++)
#pragma unroll
                for (int nt = 0; nt < 8; nt++)
                    mma_tf32(acc[mt][nt], a[mt], b[nt]);
        }
    }

#pragma unroll
    for (int mt = 0; mt < 2; mt++) {
        int r = row0 + wm * 32 + mt * 16 + (lane >> 2);
#pragma unroll
        for (int nt = 0; nt < 8; nt++) {
            int c = n0 + wn * 64 + nt * 8 + 2 * (lane & 3);
            *(float2*)&g_h[(size_t)r * HID + c] =
                make_float2(acc[mt][nt][0], acc[mt][nt][1]);
            *(float2*)&g_h[(size_t)(r + 8) * HID + c] =
                make_float2(acc[mt][nt][2], acc[mt][nt][3]);
        }
    }
}

// ===========================================================================
// K4: per-b attention block, looping 8 heads. adj converted ONCE into a
// 4 KB smem mask (uint8, pads=0) — kills the 8x re-read of adj from DRAM
// and cuts grid 16384 -> 2048. Per-head math identical to round-11 k4.
// ===========================================================================
#define HS_STR 72
#define ES_STR 68

__global__ __launch_bounds__(256) void k4_attn(
    const int* __restrict__ adj, const float* __restrict__ a_l)
{
    __shared__ float hs[64][HS_STR];
    __shared__ float es[64][ES_STR];
    __shared__ unsigned char mask[64 * 64];
    __shared__ float asv[2 * FOUT];
    __shared__ float f1[64], f2[64];
    __shared__ float ps[4][64];
    __shared__ float rsv[64];

    const int b    = blockIdx.x;
    const int tid  = threadIdx.x;
    const int lane = tid & 31;
    const int wid  = tid >> 5;

    // adj -> smem mask once per b (pads i,j >= 62 are 0)
    const int* adjb = adj + (size_t)b * NN * NN;
    for (int idx = tid; idx < 64 * 64; idx += 256) {
        int i = idx >> 6, j = idx & 63;
        mask[idx] = (i < NN && j < NN && adjb[i * NN + j] > 0) ? 1 : 0;
    }

    const float* hrow = &g_h[(size_t)b * NN * HID];
    float* orow = &g_hx[(size_t)b * NN * HID];

#pragma unroll 1
    for (int head = 0; head < HEADS; head++) {
        __syncthreads();   // protect hs/es/asv from previous head's readers

        // load h tile for this head (zero pad rows 62,63)
        const float* hbase = hrow + head * FOUT;
        for (int idx = tid; idx < 64 * 16; idx += 256) {
            int j = idx >> 4, d4 = idx & 15;
            float4 v = (j < NN) ? *(const float4*)(hbase + (size_t)j * HID + d4 * 4)
                                : make_float4(0.f, 0.f, 0.f, 0.f);
            *(float4*)&hs[j][d4 * 4] = v;
        }
        if (tid < 2 * FOUT) asv[tid] = a_l[head * 2 * FOUT + tid];
        __syncthreads();

        // f1/f2: 4 threads per node, quad shfl reduce
        {
            int node = tid >> 2, t = tid & 3;
            float s1 = 0.f, s2 = 0.f;
#pragma unroll
            for (int dd = 0; dd < 16; dd++) {
                int d = t * 16 + dd;
                float v = hs[node][d];
                s1 += v * asv[d];
                s2 += v * asv[FOUT + d];
            }
            s1 += __shfl_xor_sync(0xffffffffu, s1, 1);
            s1 += __shfl_xor_sync(0xffffffffu, s1, 2);
            s2 += __shfl_xor_sync(0xffffffffu, s2, 1);
            s2 += __shfl_xor_sync(0xffffffffu, s2, 2);
            if (t == 0) { f1[node] = s1; f2[node] = s2; }
        }
        __syncthreads();

        // es[i][j] = tf32r(exp(leaky(f2[i]+f1[j]))) if mask else 0
        for (int idx = tid; idx < 64 * 64; idx += 256) {
            int i = idx >> 6, j = idx & 63;
            float e = 0.f;
            if (mask[idx]) {
                float v = f2[i] + f1[j];
                v = v > 0.f ? v : 0.2f * v;
                e = tf32r(__expf(v));
            }
            es[i][j] = e;
        }
        __syncthreads();

        // column sums over i (softmax axis), 4 threads per column
        {
            int j = tid & 63, q = tid >> 6;
            float s = 0.f;
#pragma unroll
            for (int ii = 0; ii < 16; ii++) s += es[q + ii * 4][j];
            ps[q][j] = s;
        }
        __syncthreads();
        if (tid < 64) {
            float s = ps[0][tid] + ps[1][tid] + ps[2][tid] + ps[3][tid];
            rsv[tid] = (s > 0.f) ? 1.f / s : 0.f;
        }
        __syncthreads();

        // fold 1/colsum[j] into hs row j, round to tf32
        for (int idx = tid; idx < 64 * 16; idx += 256) {
            int j = idx >> 4, d4 = idx & 15;
            float rs = rsv[j];
            float4 v = *(float4*)&hs[j][d4 * 4];
            v.x = tf32r(v.x * rs); v.y = tf32r(v.y * rs);
            v.z = tf32r(v.z * rs); v.w = tf32r(v.w * rs);
            *(float4*)&hs[j][d4 * 4] = v;
        }
        __syncthreads();

        // tensor-core aggregation D = es @ hs, then ELU + store
        {
            const int wm = wid & 3, wn = wid >> 2;
            float acc[4][4];
#pragma unroll
            for (int nt = 0; nt < 4; nt++)
#pragma unroll
                for (int q = 0; q < 4; q++) acc[nt][q] = 0.f;

            const int r = wm * 16 + (lane >> 2);
#pragma unroll
            for (int kb = 0; kb < 64; kb += 8) {
                const int k = kb + (lane & 3);
                uint32_t a[4];
                a[0] = __float_as_uint(es[r][k]);
                a[1] = __float_as_uint(es[r + 8][k]);
                a[2] = __float_as_uint(es[r][k + 4]);
                a[3] = __float_as_uint(es[r + 8][k + 4]);
#pragma unroll
                for (int nt = 0; nt < 4; nt++) {
                    const int c = wn * 32 + nt * 8 + (lane >> 2);
                    uint32_t bb[2];
                    bb[0] = __float_as_uint(hs[k][c]);
                    bb[1] = __float_as_uint(hs[k + 4][c]);
                    mma_tf32(acc[nt], a, bb);
                }
            }

            const int i0 = wm * 16 + (lane >> 2);
            const int i1 = i0 + 8;
            float* ob = orow + head * FOUT;
#pragma unroll
            for (int nt = 0; nt < 4; nt++) {
                int c = wn * 32 + nt * 8 + 2 * (lane & 3);
                float v0 = acc[nt][0], v1 = acc[nt][1];
                v0 = v0 > 0.f ? v0 : expm1f(v0);
                v1 = v1 > 0.f ? v1 : expm1f(v1);
                *(float2*)(ob + (size_t)i0 * HID + c) =
                    make_float2(tf32r(v0), tf32r(v1));
                if (i1 < NN) {
                    float v2 = acc[nt][2], v3 = acc[nt][3];
                    v2 = v2 > 0.f ? v2 : expm1f(v2);
                    v3 = v3 > 0.f ? v3 : expm1f(v3);
                    *(float2*)(ob + (size_t)i1 * HID + c) =
                        make_float2(tf32r(v2), tf32r(v3));
                }
            }
        }
    }
}

// ===========================================================================
// K5: pool + output head + log_softmax
// ===========================================================================
__global__ __launch_bounds__(512) void k5_out(
    const float* __restrict__ Wout, const float* __restrict__ bout,
    float* __restrict__ out)
{
    int b = blockIdx.x, tid = threadIdx.x;
    int lane = tid & 31, wid = tid >> 5;
    const float* hb = &g_hx[(size_t)b * NN * HID];
    float s = 0.f;
    for (int n = 0; n < NN; n++) s += hb[(size_t)n * HID + tid];

    float v0 = s * Wout[tid * 3 + 0];
    float v1 = s * Wout[tid * 3 + 1];
    float v2 = s * Wout[tid * 3 + 2];
#pragma unroll
    for (int off = 16; off > 0; off >>= 1) {
        v0 += __shfl_down_sync(0xffffffffu, v0, off);
        v1 += __shfl_down_sync(0xffffffffu, v1, off);
        v2 += __shfl_down_sync(0xffffffffu, v2, off);
    }
    __shared__ float red[3][16];
    if (lane == 0) { red[0][wid] = v0; red[1][wid] = v1; red[2][wid] = v2; }
    __syncthreads();
    if (tid == 0) {
        float lg[3];
#pragma unroll
        for (int c = 0; c < 3; c++) {
            float t = 0.f;
#pragma unroll
            for (int w = 0; w < 16; w++) t += red[c][w];
            lg[c] = t + bout[c];
        }
        float m = fmaxf(lg[0], fmaxf(lg[1], lg[2]));
        float sum = expf(lg[0] - m) + expf(lg[1] - m) + expf(lg[2] - m);
        float lse = logf(sum) + m;
        out[b * 3 + 0] = lg[0] - lse;
        out[b * 3 + 1] = lg[1] - lse;
        out[b * 3 + 2] = lg[2] - lse;
    }
}

// ===========================================================================
extern "C" void kernel_launch(void* const* d_in, const int* in_sizes, int n_in,
                              void* d_out, int out_size)
{
    const float* x     = (const float*)d_in[0];
    const int*   adj   = (const int*)  d_in[1];
    const float* gamma = (const float*)d_in[2];
    const float* beta  = (const float*)d_in[3];
    const float* mean  = (const float*)d_in[4];
    const float* var   = (const float*)d_in[5];
    const float* Wm    = (const float*)d_in[6];
    const float* bm    = (const float*)d_in[7];
    const float* Wg    = (const float*)d_in[8];
    const float* ag    = (const float*)d_in[9];
    const float* Wo    = (const float*)d_in[10];
    const float* bo    = (const float*)d_in[11];
    float* out = (float*)d_out;

    cudaFuncSetAttribute(k2_mma, cudaFuncAttributeMaxDynamicSharedMemorySize, K2_SMEM);
    cudaFuncSetAttribute(k1_mma, cudaFuncAttributeMaxDynamicSharedMemorySize, K2_SMEM);

    k0_round_w<<<(3 * HEADS * HID * FOUT + 1023) / 1024, 1024>>>(Wg);
    k0_round_wm<<<(FIN * HID + 1023) / 1024, 1024>>>(Wm);
    k0_colsum_wm<<<1, HID>>>();

    k1_mma<<<dim3(HID / TN, NROWS / TM), 256, K2_SMEM>>>(x, gamma, beta, mean, var, bm);

    for (int l = 0; l < 3; l++) {
        k2_mma<<<dim3(HID / TN, NROWS / TM), 256, K2_SMEM>>>(l);
        k4_attn<<<BB, 256>>>(adj, ag + (size_t)l * HEADS * 2 * FOUT);
    }

    k5_out<<<BB, 512>>>(Wo, bo, out);
}

// round 13
// speedup vs baseline: 1.3998x; 1.0501x over previous
#include <cuda_runtime.h>
#include <math.h>
#include <cstdint>

#define BB    2048
#define NN    62
#define FIN   128
#define HID   512
#define HEADS 8
#define FOUT  64
#define NROWS (BB * NN)   // 126976

__device__ float g_hx[(size_t)NROWS * HID];
__device__ float g_h [(size_t)NROWS * HID];
__device__ float g_Wmr[FIN * HID];
__device__ float g_cs[HID];
// packed weights: smem-image layout [tile][stage][g][c][t] of float2 pairs
// pair = (W[k0+t][col], W[k0+4+t][col]), k0 = stage*32 + g*8, col = tile*128+c
__device__ float2 g_Wp2[3 * 4 * 16 * 4 * 128 * 4];   // GAT W, 3 layers
__device__ float2 g_Wp1[4 * 4 * 4 * 128 * 4];        // W_mlp

// ===========================================================================
// helpers
// ===========================================================================
__device__ __forceinline__ uint32_t smem_u32(const void* p) {
    uint32_t a;
    asm("{ .reg .u64 t; cvta.to.shared.u64 t, %1; cvt.u32.u64 %0, t; }"
        : "=r"(a) : "l"(p));
    return a;
}
__device__ __forceinline__ float tf32r(float x) {
    uint32_t u;
    asm("cvt.rna.tf32.f32 %0, %1;" : "=r"(u) : "f"(x));
    return __uint_as_float(u);
}
__device__ __forceinline__ uint32_t tf32u(float x) {
    uint32_t u;
    asm("cvt.rna.tf32.f32 %0, %1;" : "=r"(u) : "f"(x));
    return u;
}
__device__ __forceinline__ void cp_async16(uint32_t dst, const void* src) {
    asm volatile("cp.async.cg.shared.global [%0], [%1], 16;"
                 :: "r"(dst), "l"(src) : "memory");
}
__device__ __forceinline__ void cp_commit() {
    asm volatile("cp.async.commit_group;" ::: "memory");
}
template <int N>
__device__ __forceinline__ void cp_wait() {
    asm volatile("cp.async.wait_group %0;" :: "n"(N) : "memory");
}
__device__ __forceinline__ void mma_tf32(float* c, const uint32_t* a, const uint32_t* b) {
    asm volatile(
        "mma.sync.aligned.m16n8k8.row.col.f32.tf32.tf32.f32 "
        "{%0,%1,%2,%3}, {%4,%5,%6,%7}, {%8,%9}, {%0,%1,%2,%3};"
        : "+f"(c[0]), "+f"(c[1]), "+f"(c[2]), "+f"(c[3])
        : "r"(a[0]), "r"(a[1]), "r"(a[2]), "r"(a[3]), "r"(b[0]), "r"(b[1]));
}

// ===========================================================================
// K0: weight packing (one-time)
// ===========================================================================
__global__ void k0_pack_w2(const float* __restrict__ Wg) {
    int idx = blockIdx.x * 256 + threadIdx.x;     // [3][4][16][4][128][4]
    if (idx >= 3 * 4 * 16 * 4 * 128 * 4) return;
    int t    = idx & 3;
    int c    = (idx >> 2) & 127;
    int g    = (idx >> 9) & 3;
    int s    = (idx >> 11) & 15;
    int tile = (idx >> 15) & 3;
    int l    = idx >> 17;
    int col  = tile * 128 + c;
    int head = col >> 6, d = col & 63;
    int k    = s * 32 + g * 8 + t;
    const float* W = Wg + ((size_t)l * HEADS + head) * HID * FOUT;
    g_Wp2[idx] = make_float2(tf32r(W[(size_t)k * FOUT + d]),
                             tf32r(W[(size_t)(k + 4) * FOUT + d]));
}
__global__ void k0_pack_w1(const float* __restrict__ Wm) {
    int idx = blockIdx.x * 256 + threadIdx.x;     // [4][4][4][128][4]
    if (idx >= 4 * 4 * 4 * 128 * 4) return;
    int t    = idx & 3;
    int c    = (idx >> 2) & 127;
    int g    = (idx >> 9) & 3;
    int s    = (idx >> 11) & 3;
    int tile = idx >> 13;
    int col  = tile * 128 + c;
    int k    = s * 32 + g * 8 + t;
    g_Wp1[idx] = make_float2(tf32r(Wm[(size_t)k * HID + col]),
                             tf32r(Wm[(size_t)(k + 4) * HID + col]));
}
__global__ void k0_round_wm(const float* __restrict__ Wm) {
    int i = blockIdx.x * 1024 + threadIdx.x;
    if (i < FIN * HID) g_Wmr[i] = tf32r(Wm[i]);
}
__global__ void k0_colsum_wm() {
    int c = threadIdx.x;
    float s = 0.f;
    for (int k = 0; k < FIN; k++) s += g_Wmr[k * HID + c];
    g_cs[c] = s;
}

// ===========================================================================
// shared GEMM tile config — packed B: stage = A(18432) + B(16384) = 34816
// NBUF=3 -> 104448 B -> 2 CTAs/SM
// ===========================================================================
#define TM 128
#define TN 128
#define KC 32
#define NBUF 3
#define A_STRIDE 36
#define A_BYTES (TM * A_STRIDE * 4)        // 18432
#define B_BYTES 16384
#define STAGE_BYTES (A_BYTES + B_BYTES)    // 34816
#define K2_SMEM (NBUF * STAGE_BYTES)       // 104448

__device__ __forceinline__ int slot3(int s) { return s - (s / 3) * 3; }

// ===========================================================================
// K1M (tf32 mma): h_x = s_row*(x @ Wm) + t_row*colsum(Wm) + b  (packed B)
// ===========================================================================
__global__ __launch_bounds__(256, 2) void k1_mma(
    const float* __restrict__ x,
    const float* __restrict__ gamma, const float* __restrict__ beta,
    const float* __restrict__ mean,  const float* __restrict__ var,
    const float* __restrict__ bm)
{
    extern __shared__ __align__(16) char smem[];
    const int NS_K = FIN / KC;   // 4
    const int tid  = threadIdx.x;
    const int lane = tid & 31;
    const int wid  = tid >> 5;
    const int wm   = wid & 3;
    const int wn   = wid >> 2;
    const int tile = blockIdx.x;
    const int n0   = tile * TN;
    const int row0 = blockIdx.y * TM;
    const uint32_t sbase = smem_u32(smem);

    auto issue_stage = [&](int s) {
        const int p = slot3(s);
        const float* Ag = x + (size_t)row0 * FIN + s * KC;
        const uint32_t Ad = sbase + p * STAGE_BYTES;
#pragma unroll
        for (int i = 0; i < 4; i++) {
            int idx = tid + i * 256;
            int r = idx >> 3, k4 = idx & 7;
            cp_async16(Ad + r * (A_STRIDE * 4) + k4 * 16,
                       Ag + (size_t)r * FIN + k4 * 4);
        }
        const uint32_t Bd = sbase + p * STAGE_BYTES + A_BYTES;
        const char* Bsrc = (const char*)(g_Wp1 + ((size_t)(tile * 4 + s)) * 2048);
#pragma unroll
        for (int i = 0; i < 4; i++) {
            int idx = tid + i * 256;
            cp_async16(Bd + idx * 16, Bsrc + idx * 16);
        }
    };

    float acc[2][8][4];
#pragma unroll
    for (int mt = 0; mt < 2; mt++)
#pragma unroll
        for (int nt = 0; nt < 8; nt++)
#pragma unroll
            for (int q = 0; q < 4; q++) acc[mt][nt][q] = 0.f;

#pragma unroll
    for (int s = 0; s < NBUF - 1; s++) { issue_stage(s); cp_commit(); }

#pragma unroll 1
    for (int s = 0; s < NS_K; s++) {
        if (s < NS_K - 1) cp_wait<1>();
        else              cp_wait<0>();
        __syncthreads();
        if (s + NBUF - 1 < NS_K) issue_stage(s + NBUF - 1);
        cp_commit();

        const float* As = (const float*)(smem + slot3(s) * STAGE_BYTES);
        const float2* Bp = (const float2*)((const char*)As + A_BYTES);

#pragma unroll
        for (int ks = 0; ks < KC / 8; ks++) {
            const int kb = ks * 8;
            uint32_t a[2][4], b[8][2];
#pragma unroll
            for (int mt = 0; mt < 2; mt++) {
                int r = wm * 32 + mt * 16 + (lane >> 2);
                int k = kb + (lane & 3);
                a[mt][0] = tf32u(As[r * A_STRIDE + k]);
                a[mt][1] = tf32u(As[(r + 8) * A_STRIDE + k]);
                a[mt][2] = tf32u(As[r * A_STRIDE + k + 4]);
                a[mt][3] = tf32u(As[(r + 8) * A_STRIDE + k + 4]);
            }
#pragma unroll
            for (int nt = 0; nt < 8; nt++) {
                int c = wn * 64 + nt * 8 + (lane >> 2);
                float2 v = Bp[(ks * 128 + c) * 4 + (lane & 3)];
                b[nt][0] = __float_as_uint(v.x);
                b[nt][1] = __float_as_uint(v.y);
            }
#pragma unroll
            for (int mt = 0; mt < 2; mt++)
#pragma unroll
                for (int nt = 0; nt < 8; nt++)
                    mma_tf32(acc[mt][nt], a[mt], b[nt]);
        }
    }

    const int rbase = wm * 32 + (lane >> 2);
    float sv[4], tv[4];
#pragma unroll
    for (int q = 0; q < 4; q++) {
        int r = row0 + rbase + q * 8;
        int n = r % NN;
        float sc = gamma[n] * rsqrtf(var[n] + 1e-5f);
        sv[q] = sc;
        tv[q] = beta[n] - mean[n] * sc;
    }
#pragma unroll
    for (int mt = 0; mt < 2; mt++) {
        int r = row0 + rbase + mt * 16;
#pragma unroll
        for (int nt = 0; nt < 8; nt++) {
            int c = n0 + wn * 64 + nt * 8 + 2 * (lane & 3);
            float cs0 = g_cs[c], cs1 = g_cs[c + 1];
            float b0 = bm[c], b1 = bm[c + 1];
            int q0 = mt * 2, q1 = mt * 2 + 1;
            *(float2*)&g_hx[(size_t)r * HID + c] = make_float2(
                tf32r(sv[q0] * acc[mt][nt][0] + tv[q0] * cs0 + b0),
                tf32r(sv[q0] * acc[mt][nt][1] + tv[q0] * cs1 + b1));
            *(float2*)&g_hx[(size_t)(r + 8) * HID + c] = make_float2(
                tf32r(sv[q1] * acc[mt][nt][2] + tv[q1] * cs0 + b0),
                tf32r(sv[q1] * acc[mt][nt][3] + tv[q1] * cs1 + b1));
        }
    }
}

// ===========================================================================
// K2 (tf32 mma, packed B): g_h = g_hx @ W_gat[l]
// ===========================================================================
__global__ __launch_bounds__(256, 2) void k2_mma(int layer)
{
    extern __shared__ __align__(16) char smem[];
    const int NS_K = HID / KC;   // 16
    const int tid  = threadIdx.x;
    const int lane = tid & 31;
    const int wid  = tid >> 5;
    const int wm   = wid & 3;
    const int wn   = wid >> 2;
    const int tile = blockIdx.x;
    const int n0   = tile * TN;
    const int row0 = blockIdx.y * TM;
    const uint32_t sbase = smem_u32(smem);
    const float2* Wp = g_Wp2 + ((size_t)(layer * 4 + tile) * 16) * 2048;

    auto issue_stage = [&](int s) {
        const int p = slot3(s);
        const float* Ag = g_hx + (size_t)row0 * HID + s * KC;
        const uint32_t Ad = sbase + p * STAGE_BYTES;
#pragma unroll
        for (int i = 0; i < 4; i++) {
            int idx = tid + i * 256;
            int r = idx >> 3, k4 = idx & 7;
            cp_async16(Ad + r * (A_STRIDE * 4) + k4 * 16,
                       Ag + (size_t)r * HID + k4 * 4);
        }
        const uint32_t Bd = sbase + p * STAGE_BYTES + A_BYTES;
        const char* Bsrc = (const char*)(Wp + (size_t)s * 2048);
#pragma unroll
        for (int i = 0; i < 4; i++) {
            int idx = tid + i * 256;
            cp_async16(Bd + idx * 16, Bsrc + idx * 16);
        }
    };

    float acc[2][8][4];
#pragma unroll
    for (int mt = 0; mt < 2; mt++)
#pragma unroll
        for (int nt = 0; nt < 8; nt++)
#pragma unroll
            for (int q = 0; q < 4; q++) acc[mt][nt][q] = 0.f;

#pragma unroll
    for (int s = 0; s < NBUF - 1; s++) { issue_stage(s); cp_commit(); }

#pragma unroll 1
    for (int s = 0; s < NS_K; s++) {
        if (s < NS_K - 1) cp_wait<1>();
        else              cp_wait<0>();
        __syncthreads();
        if (s + NBUF - 1 < NS_K) issue_stage(s + NBUF - 1);
        cp_commit();

        const float* As = (const float*)(smem + slot3(s) * STAGE_BYTES);
        const float2* Bp = (const float2*)((const char*)As + A_BYTES);

#pragma unroll
        for (int ks = 0; ks < KC / 8; ks++) {
            const int kb = ks * 8;
            uint32_t a[2][4], b[8][2];
#pragma unroll
            for (int mt = 0; mt < 2; mt++) {
                int r = wm * 32 + mt * 16 + (lane >> 2);
                int k = kb + (lane & 3);
                a[mt][0] = __float_as_uint(As[r * A_STRIDE + k]);
                a[mt][1] = __float_as_uint(As[(r + 8) * A_STRIDE + k]);
                a[mt][2] = __float_as_uint(As[r * A_STRIDE + k + 4]);
                a[mt][3] = __float_as_uint(As[(r + 8) * A_STRIDE + k + 4]);
            }
#pragma unroll
            for (int nt = 0; nt < 8; nt++) {
                int c = wn * 64 + nt * 8 + (lane >> 2);
                float2 v = Bp[(ks * 128 + c) * 4 + (lane & 3)];
                b[nt][0] = __float_as_uint(v.x);
                b[nt][1] = __float_as_uint(v.y);
            }
#pragma unroll
            for (int mt = 0; mt < 2; mt++)
#pragma unroll
                for (int nt = 0; nt < 8; nt++)
                    mma_tf32(acc[mt][nt], a[mt], b[nt]);
        }
    }

#pragma unroll
    for (int mt = 0; mt < 2; mt++) {
        int r = row0 + wm * 32 + mt * 16 + (lane >> 2);
#pragma unroll
        for (int nt = 0; nt < 8; nt++) {
            int c = n0 + wn * 64 + nt * 8 + 2 * (lane & 3);
            *(float2*)&g_h[(size_t)r * HID + c] =
                make_float2(acc[mt][nt][0], acc[mt][nt][1]);
            *(float2*)&g_h[(size_t)(r + 8) * HID + c] =
                make_float2(acc[mt][nt][2], acc[mt][nt][3]);
        }
    }
}

// ===========================================================================
// K4: per-b attention, 8-head loop, smem adj mask (round-12 version)
// ===========================================================================
#define HS_STR 72
#define ES_STR 68

__global__ __launch_bounds__(256) void k4_attn(
    const int* __restrict__ adj, const float* __restrict__ a_l)
{
    __shared__ float hs[64][HS_STR];
    __shared__ float es[64][ES_STR];
    __shared__ unsigned char mask[64 * 64];
    __shared__ float asv[2 * FOUT];
    __shared__ float f1[64], f2[64];
    __shared__ float ps[4][64];
    __shared__ float rsv[64];

    const int b    = blockIdx.x;
    const int tid  = threadIdx.x;
    const int lane = tid & 31;
    const int wid  = tid >> 5;

    const int* adjb = adj + (size_t)b * NN * NN;
    for (int idx = tid; idx < 64 * 64; idx += 256) {
        int i = idx >> 6, j = idx & 63;
        mask[idx] = (i < NN && j < NN && adjb[i * NN + j] > 0) ? 1 : 0;
    }

    const float* hrow = &g_h[(size_t)b * NN * HID];
    float* orow = &g_hx[(size_t)b * NN * HID];

#pragma unroll 1
    for (int head = 0; head < HEADS; head++) {
        __syncthreads();

        const float* hbase = hrow + head * FOUT;
        for (int idx = tid; idx < 64 * 16; idx += 256) {
            int j = idx >> 4, d4 = idx & 15;
            float4 v = (j < NN) ? *(const float4*)(hbase + (size_t)j * HID + d4 * 4)
                                : make_float4(0.f, 0.f, 0.f, 0.f);
            *(float4*)&hs[j][d4 * 4] = v;
        }
        if (tid < 2 * FOUT) asv[tid] = a_l[head * 2 * FOUT + tid];
        __syncthreads();

        {
            int node = tid >> 2, t = tid & 3;
            float s1 = 0.f, s2 = 0.f;
#pragma unroll
            for (int dd = 0; dd < 16; dd++) {
                int d = t * 16 + dd;
                float v = hs[node][d];
                s1 += v * asv[d];
                s2 += v * asv[FOUT + d];
            }
            s1 += __shfl_xor_sync(0xffffffffu, s1, 1);
            s1 += __shfl_xor_sync(0xffffffffu, s1, 2);
            s2 += __shfl_xor_sync(0xffffffffu, s2, 1);
            s2 += __shfl_xor_sync(0xffffffffu, s2, 2);
            if (t == 0) { f1[node] = s1; f2[node] = s2; }
        }
        __syncthreads();

        for (int idx = tid; idx < 64 * 64; idx += 256) {
            int i = idx >> 6, j = idx & 63;
            float e = 0.f;
            if (mask[idx]) {
                float v = f2[i] + f1[j];
                v = v > 0.f ? v : 0.2f * v;
                e = tf32r(__expf(v));
            }
            es[i][j] = e;
        }
        __syncthreads();

        {
            int j = tid & 63, q = tid >> 6;
            float s = 0.f;
#pragma unroll
            for (int ii = 0; ii < 16; ii++) s += es[q + ii * 4][j];
            ps[q][j] = s;
        }
        __syncthreads();
        if (tid < 64) {
            float s = ps[0][tid] + ps[1][tid] + ps[2][tid] + ps[3][tid];
            rsv[tid] = (s > 0.f) ? 1.f / s : 0.f;
        }
        __syncthreads();

        for (int idx = tid; idx < 64 * 16; idx += 256) {
            int j = idx >> 4, d4 = idx & 15;
            float rs = rsv[j];
            float4 v = *(float4*)&hs[j][d4 * 4];
            v.x = tf32r(v.x * rs); v.y = tf32r(v.y * rs);
            v.z = tf32r(v.z * rs); v.w = tf32r(v.w * rs);
            *(float4*)&hs[j][d4 * 4] = v;
        }
        __syncthreads();

        {
            const int wm = wid & 3, wn = wid >> 2;
            float acc[4][4];
#pragma unroll
            for (int nt = 0; nt < 4; nt++)
#pragma unroll
                for (int q = 0; q < 4; q++) acc[nt][q] = 0.f;

            const int r = wm * 16 + (lane >> 2);
#pragma unroll
            for (int kb = 0; kb < 64; kb += 8) {
                const int k = kb + (lane & 3);
                uint32_t a[4];
                a[0] = __float_as_uint(es[r][k]);
                a[1] = __float_as_uint(es[r + 8][k]);
                a[2] = __float_as_uint(es[r][k + 4]);
                a[3] = __float_as_uint(es[r + 8][k + 4]);
#pragma unroll
                for (int nt = 0; nt < 4; nt++) {
                    const int c = wn * 32 + nt * 8 + (lane >> 2);
                    uint32_t bb[2];
                    bb[0] = __float_as_uint(hs[k][c]);
                    bb[1] = __float_as_uint(hs[k + 4][c]);
                    mma_tf32(acc[nt], a, bb);
                }
            }

            const int i0 = wm * 16 + (lane >> 2);
            const int i1 = i0 + 8;
            float* ob = orow + head * FOUT;
#pragma unroll
            for (int nt = 0; nt < 4; nt++) {
                int c = wn * 32 + nt * 8 + 2 * (lane & 3);
                float v0 = acc[nt][0], v1 = acc[nt][1];
                v0 = v0 > 0.f ? v0 : expm1f(v0);
                v1 = v1 > 0.f ? v1 : expm1f(v1);
                *(float2*)(ob + (size_t)i0 * HID + c) =
                    make_float2(tf32r(v0), tf32r(v1));
                if (i1 < NN) {
                    float v2 = acc[nt][2], v3 = acc[nt][3];
                    v2 = v2 > 0.f ? v2 : expm1f(v2);
                    v3 = v3 > 0.f ? v3 : expm1f(v3);
                    *(float2*)(ob + (size_t)i1 * HID + c) =
                        make_float2(tf32r(v2), tf32r(v3));
                }
            }
        }
    }
}

// ===========================================================================
// K5: pool + output head + log_softmax
// ===========================================================================
__global__ __launch_bounds__(512) void k5_out(
    const float* __restrict__ Wout, const float* __restrict__ bout,
    float* __restrict__ out)
{
    int b = blockIdx.x, tid = threadIdx.x;
    int lane = tid & 31, wid = tid >> 5;
    const float* hb = &g_hx[(size_t)b * NN * HID];
    float s = 0.f;
    for (int n = 0; n < NN; n++) s += hb[(size_t)n * HID + tid];

    float v0 = s * Wout[tid * 3 + 0];
    float v1 = s * Wout[tid * 3 + 1];
    float v2 = s * Wout[tid * 3 + 2];
#pragma unroll
    for (int off = 16; off > 0; off >>= 1) {
        v0 += __shfl_down_sync(0xffffffffu, v0, off);
        v1 += __shfl_down_sync(0xffffffffu, v1, off);
        v2 += __shfl_down_sync(0xffffffffu, v2, off);
    }
    __shared__ float red[3][16];
    if (lane == 0) { red[0][wid] = v0; red[1][wid] = v1; red[2][wid] = v2; }
    __syncthreads();
    if (tid == 0) {
        float lg[3];
#pragma unroll
        for (int c = 0; c < 3; c++) {
            float t = 0.f;
#pragma unroll
            for (int w = 0; w < 16; w++) t += red[c][w];
            lg[c] = t + bout[c];
        }
        float m = fmaxf(lg[0], fmaxf(lg[1], lg[2]));
        float sum = expf(lg[0] - m) + expf(lg[1] - m) + expf(lg[2] - m);
        float lse = logf(sum) + m;
        out[b * 3 + 0] = lg[0] - lse;
        out[b * 3 + 1] = lg[1] - lse;
        out[b * 3 + 2] = lg[2] - lse;
    }
}

// ===========================================================================
extern "C" void kernel_launch(void* const* d_in, const int* in_sizes, int n_in,
                              void* d_out, int out_size)
{
    const float* x     = (const float*)d_in[0];
    const int*   adj   = (const int*)  d_in[1];
    const float* gamma = (const float*)d_in[2];
    const float* beta  = (const float*)d_in[3];
    const float* mean  = (const float*)d_in[4];
    const float* var   = (const float*)d_in[5];
    const float* Wm    = (const float*)d_in[6];
    const float* bm    = (const float*)d_in[7];
    const float* Wg    = (const float*)d_in[8];
    const float* ag    = (const float*)d_in[9];
    const float* Wo    = (const float*)d_in[10];
    const float* bo    = (const float*)d_in[11];
    float* out = (float*)d_out;

    cudaFuncSetAttribute(k2_mma, cudaFuncAttributeMaxDynamicSharedMemorySize, K2_SMEM);
    cudaFuncSetAttribute(k1_mma, cudaFuncAttributeMaxDynamicSharedMemorySize, K2_SMEM);

    k0_pack_w2<<<(3 * 4 * 16 * 4 * 128 * 4) / 256, 256>>>(Wg);
    k0_pack_w1<<<(4 * 4 * 4 * 128 * 4) / 256, 256>>>(Wm);
    k0_round_wm<<<(FIN * HID + 1023) / 1024, 1024>>>(Wm);
    k0_colsum_wm<<<1, HID>>>();

    k1_mma<<<dim3(HID / TN, NROWS / TM), 256, K2_SMEM>>>(x, gamma, beta, mean, var, bm);

    for (int l = 0; l < 3; l++) {
        k2_mma<<<dim3(HID / TN, NROWS / TM), 256, K2_SMEM>>>(l);
        k4_attn<<<BB, 256>>>(adj, ag + (size_t)l * HEADS * 2 * FOUT);
    }

    k5_out<<<BB, 512>>>(Wo, bo, out);
}